// round 1
// baseline (speedup 1.0000x reference)
#include <cuda_runtime.h>

#define NL 14

struct Params {
    const float* x;
    const float* w[NL];
    const float* b[NL];
    float* out;
    int n;
};

// Packed dual-row fp32 FMA: d = a*b + c on both halves (Blackwell FFMA2).
__device__ __forceinline__ float2 ffma2(float2 a, float2 b, float2 c) {
    float2 d;
    asm("{\n\t"
        ".reg .b64 ra, rb, rc;\n\t"
        "mov.b64 ra, {%2, %3};\n\t"
        "mov.b64 rb, {%4, %5};\n\t"
        "mov.b64 rc, {%6, %7};\n\t"
        "fma.rn.f32x2 rc, ra, rb, rc;\n\t"
        "mov.b64 {%0, %1}, rc;\n\t"
        "}"
        : "=f"(d.x), "=f"(d.y)
        : "f"(a.x), "f"(a.y), "f"(b.x), "f"(b.y), "f"(c.x), "f"(c.y));
    return d;
}

// One linear layer on a packed row-pair.
// Weights come pre-duplicated in shared: float4 {w[j,2m],w[j,2m],w[j,2m+1],w[j,2m+1]}
// so one LDS.128 feeds two FFMA2s. Bias pre-duplicated as float2 {b,b}.
template<int DIN, int DOUT, bool RELU, bool SKIP>
__device__ __forceinline__ void run_layer(const float4* __restrict__ w4,
                                          const float2* __restrict__ bb,
                                          const float2* hin, float2* hout,
                                          const float2* skip)
{
    constexpr int DP2 = (DIN + 1) / 2;
#pragma unroll
    for (int j = 0; j < DOUT; ++j) {
        float2 acc = bb[j];
        if constexpr (SKIP) {
            acc = ffma2(skip[j], make_float2(1.f, 1.f), acc);
        }
#pragma unroll
        for (int m = 0; m < DP2; ++m) {
            float4 w = w4[j * DP2 + m];
            acc = ffma2(hin[2 * m], make_float2(w.x, w.y), acc);
            if (2 * m + 1 < DIN)
                acc = ffma2(hin[2 * m + 1], make_float2(w.z, w.w), acc);
        }
        if constexpr (RELU) {
            acc.x = fmaxf(acc.x, 0.f);
            acc.y = fmaxf(acc.y, 0.f);
        }
        hout[j] = acc;
    }
}

__global__ void __launch_bounds__(128) csnet14_kernel(Params p)
{
    // Shared weight staging: 613 float4 slots + 122 float2 biases (~10.8 KB).
    __shared__ float4 ws[613];
    __shared__ float2 bs[122];

    const int tid = threadIdx.x;

    // ---- cooperative weight load (compile-time-unrolled over layers) ----
    {
        const int s_din[NL]  = {12,12,11,10,9,8,7,6,7,8,9,10,11,12};
        const int s_dout[NL] = {12,11,10,9,8,7,6,7,8,9,10,11,12,2};
        const int s_w4[NL]   = {0,72,138,198,243,283,311,335,356,388,424,474,529,601};
        const int s_b[NL]    = {0,12,23,33,42,50,57,63,70,78,87,97,108,120};
#pragma unroll
        for (int L = 0; L < NL; ++L) {
            const int din = s_din[L], dout = s_dout[L];
            const int dp2 = (din + 1) >> 1;
            const float* __restrict__ w = p.w[L];
            for (int s = tid; s < dout * dp2; s += 128) {
                int j = s / dp2, m = s - j * dp2;
                float wa = w[j * din + 2 * m];
                float wb = (2 * m + 1 < din) ? w[j * din + 2 * m + 1] : 0.f;
                ws[s_w4[L] + s] = make_float4(wa, wa, wb, wb);
            }
            const float* __restrict__ bsrc = p.b[L];
            for (int s = tid; s < dout; s += 128) {
                float bv = bsrc[s];
                bs[s_b[L] + s] = make_float2(bv, bv);
            }
        }
    }
    __syncthreads();

    const int n = p.n;
    const int pairs = (n + 1) >> 1;
    const int gid = blockIdx.x * 128 + tid;
    if (gid >= pairs) return;

    const int r0 = 2 * gid;
    const int r1 = (r0 + 1 < n) ? r0 + 1 : r0;

    // ---- load 2 input rows (3x float4 each), pack feature-wise into f32x2 ----
    const float4* xa = (const float4*)(p.x + (size_t)r0 * 12);
    const float4* xb = (const float4*)(p.x + (size_t)r1 * 12);
    float4 A0 = xa[0], A1 = xa[1], A2 = xa[2];
    float4 B0 = xb[0], B1 = xb[1], B2 = xb[2];

    float2 h0[12];
    h0[0]  = make_float2(A0.x, B0.x); h0[1]  = make_float2(A0.y, B0.y);
    h0[2]  = make_float2(A0.z, B0.z); h0[3]  = make_float2(A0.w, B0.w);
    h0[4]  = make_float2(A1.x, B1.x); h0[5]  = make_float2(A1.y, B1.y);
    h0[6]  = make_float2(A1.z, B1.z); h0[7]  = make_float2(A1.w, B1.w);
    h0[8]  = make_float2(A2.x, B2.x); h0[9]  = make_float2(A2.y, B2.y);
    h0[10] = make_float2(A2.z, B2.z); h0[11] = make_float2(A2.w, B2.w);

    // ---- full network in registers ----
    float2 a1[12], a2[11], a3[10], a4[9], a5[8], a6[7], a7[6];
    float2 d8[7], d9[8], d10[9], d11[10], d12[11], d13[12], lg[2];

    run_layer<12,12,true ,false>(ws +   0, bs +   0, h0,  a1,  nullptr); // fc1
    run_layer<12,11,true ,false>(ws +  72, bs +  12, a1,  a2,  nullptr); // fc2
    run_layer<11,10,true ,false>(ws + 138, bs +  23, a2,  a3,  nullptr); // fc3
    run_layer<10, 9,true ,false>(ws + 198, bs +  33, a3,  a4,  nullptr); // fc4
    run_layer< 9, 8,true ,false>(ws + 243, bs +  42, a4,  a5,  nullptr); // fc5
    run_layer< 8, 7,true ,false>(ws + 283, bs +  50, a5,  a6,  nullptr); // fc6
    run_layer< 7, 6,true ,false>(ws + 311, bs +  57, a6,  a7,  nullptr); // fc7 (bottleneck)
    run_layer< 6, 7,true ,true >(ws + 335, bs +  63, a7,  d8,  a6);      // fc8  + id6
    run_layer< 7, 8,true ,true >(ws + 356, bs +  70, d8,  d9,  a5);      // fc9  + id5
    run_layer< 8, 9,true ,true >(ws + 388, bs +  78, d9,  d10, a4);      // fc10 + id4
    run_layer< 9,10,true ,true >(ws + 424, bs +  87, d10, d11, a3);      // fc11 + id3
    run_layer<10,11,true ,true >(ws + 474, bs +  97, d11, d12, a2);      // fc12 + id2
    run_layer<11,12,true ,true >(ws + 529, bs + 108, d12, d13, a1);      // fc13 + id1
    run_layer<12, 2,false,false>(ws + 601, bs + 120, d13, lg,  nullptr); // fc14

    // ---- softmax over 2 classes, per row ----
    float2 outA, outB;
    {
        float l0 = lg[0].x, l1 = lg[1].x;
        float m  = fmaxf(l0, l1);
        float e0 = __expf(l0 - m), e1 = __expf(l1 - m);
        float inv = __fdividef(1.f, e0 + e1);
        outA = make_float2(e0 * inv, e1 * inv);
    }
    {
        float l0 = lg[0].y, l1 = lg[1].y;
        float m  = fmaxf(l0, l1);
        float e0 = __expf(l0 - m), e1 = __expf(l1 - m);
        float inv = __fdividef(1.f, e0 + e1);
        outB = make_float2(e0 * inv, e1 * inv);
    }

    float2* o = (float2*)p.out;
    o[r0] = outA;
    o[r1] = outB;  // r1==r0 tail case writes the identical value: harmless
}

extern "C" void kernel_launch(void* const* d_in, const int* in_sizes, int n_in,
                              void* d_out, int out_size)
{
    (void)n_in; (void)out_size;
    Params p;
    p.x = (const float*)d_in[0];
#pragma unroll
    for (int i = 0; i < NL; ++i) {
        p.w[i] = (const float*)d_in[1 + 2 * i];
        p.b[i] = (const float*)d_in[2 + 2 * i];
    }
    p.out = (float*)d_out;
    p.n = in_sizes[0] / 12;

    const int pairs = (p.n + 1) / 2;
    const int blocks = (pairs + 127) / 128;
    csnet14_kernel<<<blocks, 128>>>(p);
}

// round 2
// speedup vs baseline: 1.1618x; 1.1618x over previous
#include <cuda_runtime.h>

#define NL 14
typedef unsigned long long u64;

struct Params {
    const float* x;
    const float* w[NL];
    const float* b[NL];
    float* out;
    int n;
};

// ---------- packed f32x2 helpers ----------
__device__ __forceinline__ u64 ffma2(u64 a, u64 b, u64 c) {
    u64 d;
    asm("fma.rn.f32x2 %0, %1, %2, %3;" : "=l"(d) : "l"(a), "l"(b), "l"(c));
    return d;
}
__device__ __forceinline__ u64 pk(float a, float b) {
    u64 r;
    asm("mov.b64 %0, {%1, %2};" : "=l"(r) : "f"(a), "f"(b));
    return r;
}
__device__ __forceinline__ void upk(u64 v, float& a, float& b) {
    asm("mov.b64 {%0, %1}, %2;" : "=f"(a), "=f"(b) : "l"(v));
}

// ---------- one layer, feature-packed f32x2, two rows per thread ----------
// Weights in smem as ulonglong2 per (kp, jp):
//   .x = {w[2jp,2kp],   w[2jp+1,2kp]}   (zero-padded)
//   .y = {w[2jp,2kp+1], w[2jp+1,2kp+1]}
// Activations arrive as duplicated u64s {x_k, x_k} (pad entries are {0,0}).
template<int DIN, int DOUT, bool RELU, bool SKIP, bool SAVEID, bool WDUP>
__device__ __forceinline__ void layerFP(
    const ulonglong2* __restrict__ w,
    const u64* __restrict__ bb,
    const u64* dA, const u64* dB,          // input dups, size 2*ceil(DIN/2)
    u64* oA, u64* oB,                      // output dups, size 2*ceil(DOUT/2)
    const float* skA, const float* skB,    // skip scalars (DOUT) or nullptr
    float* idA, float* idB)                // saved scalars (DOUT) or nullptr
{
    constexpr int KP = (DIN + 1) / 2;
    constexpr int JP = (DOUT + 1) / 2;
    u64 accA[JP], accB[JP];
#pragma unroll
    for (int jp = 0; jp < JP; ++jp) {
        u64 bv = bb[jp];
        accA[jp] = bv;
        accB[jp] = bv;
    }
#pragma unroll
    for (int kp = 0; kp < KP; ++kp) {
        u64 a0 = dA[2 * kp], a1 = dA[2 * kp + 1];
        u64 b0 = dB[2 * kp], b1 = dB[2 * kp + 1];
#pragma unroll
        for (int jp = 0; jp < JP; ++jp) {
            ulonglong2 ww = w[kp * JP + jp];
            accA[jp] = ffma2(a0, ww.x, accA[jp]);
            accA[jp] = ffma2(a1, ww.y, accA[jp]);
            accB[jp] = ffma2(b0, ww.x, accB[jp]);
            accB[jp] = ffma2(b1, ww.y, accB[jp]);
        }
    }
#pragma unroll
    for (int jp = 0; jp < JP; ++jp) {
        float a0, a1, b0, b1;
        upk(accA[jp], a0, a1);
        upk(accB[jp], b0, b1);
        if constexpr (SKIP) {
            a0 += skA[2 * jp];
            b0 += skB[2 * jp];
            if (2 * jp + 1 < DOUT) { a1 += skA[2 * jp + 1]; b1 += skB[2 * jp + 1]; }
        }
        if constexpr (RELU) {
            a0 = fmaxf(a0, 0.f); a1 = fmaxf(a1, 0.f);
            b0 = fmaxf(b0, 0.f); b1 = fmaxf(b1, 0.f);
        }
        if constexpr (SAVEID) {
            idA[2 * jp] = a0; idB[2 * jp] = b0;
            if (2 * jp + 1 < DOUT) { idA[2 * jp + 1] = a1; idB[2 * jp + 1] = b1; }
        }
        if constexpr (WDUP) {
            oA[2 * jp]     = pk(a0, a0);
            oA[2 * jp + 1] = pk(a1, a1);   // pad halves are 0 by construction
            oB[2 * jp]     = pk(b0, b0);
            oB[2 * jp + 1] = pk(b1, b1);
        }
    }
}

__global__ void __launch_bounds__(128) csnet14_kernel(Params p)
{
    __shared__ ulonglong2 ws[320];  // weight pairs, 5120 B
    __shared__ u64        bs[64];   // bias pairs {b_j, b_j+1}, 512 B

    const int tid = threadIdx.x;

    // ---- cooperative smem fill ----
    {
        const int s_din[NL]  = {12,12,11,10,9,8,7,6,7,8,9,10,11,12};
        const int s_dout[NL] = {12,11,10,9,8,7,6,7,8,9,10,11,12,2};
        const int s_w[NL]    = {0,36,72,102,127,147,163,175,187,203,223,248,278,314};
        const int s_b[NL]    = {0,6,12,17,22,26,30,33,37,41,46,51,57,63};
#pragma unroll
        for (int L = 0; L < NL; ++L) {
            const int din = s_din[L], dout = s_dout[L];
            const int kp_n = (din + 1) >> 1, jp_n = (dout + 1) >> 1;
            const float* __restrict__ w = p.w[L];
            float* dstf = (float*)(ws + s_w[L]);
            for (int s = tid; s < kp_n * jp_n; s += 128) {
                int kp = s / jp_n, jp = s - kp * jp_n;
                int j0 = 2 * jp, j1 = 2 * jp + 1, k0 = 2 * kp, k1 = 2 * kp + 1;
                float* d = dstf + 4 * s;
                d[0] = w[j0 * din + k0];
                d[1] = (j1 < dout) ? w[j1 * din + k0] : 0.f;
                d[2] = (k1 < din) ? w[j0 * din + k1] : 0.f;
                d[3] = (j1 < dout && k1 < din) ? w[j1 * din + k1] : 0.f;
            }
            const float* __restrict__ b = p.b[L];
            float* bf = (float*)(bs + s_b[L]);
            for (int s = tid; s < jp_n; s += 128) {
                bf[2 * s]     = b[2 * s];
                bf[2 * s + 1] = (2 * s + 1 < dout) ? b[2 * s + 1] : 0.f;
            }
        }
    }
    __syncthreads();

    const int n = p.n;
    const int pairs = (n + 1) >> 1;
    const int gid = blockIdx.x * 128 + tid;
    if (gid >= pairs) return;

    const int r0 = 2 * gid;
    const int r1 = (r0 + 1 < n) ? r0 + 1 : r0;

    // ---- input rows -> duplicated activation u64s ----
    const float4* xa = (const float4*)(p.x + (size_t)r0 * 12);
    const float4* xb = (const float4*)(p.x + (size_t)r1 * 12);
    float4 A0 = xa[0], A1 = xa[1], A2 = xa[2];
    float4 B0 = xb[0], B1 = xb[1], B2 = xb[2];

    u64 d0A[12], d0B[12];
    d0A[0]=pk(A0.x,A0.x); d0A[1]=pk(A0.y,A0.y); d0A[2]=pk(A0.z,A0.z); d0A[3]=pk(A0.w,A0.w);
    d0A[4]=pk(A1.x,A1.x); d0A[5]=pk(A1.y,A1.y); d0A[6]=pk(A1.z,A1.z); d0A[7]=pk(A1.w,A1.w);
    d0A[8]=pk(A2.x,A2.x); d0A[9]=pk(A2.y,A2.y); d0A[10]=pk(A2.z,A2.z); d0A[11]=pk(A2.w,A2.w);
    d0B[0]=pk(B0.x,B0.x); d0B[1]=pk(B0.y,B0.y); d0B[2]=pk(B0.z,B0.z); d0B[3]=pk(B0.w,B0.w);
    d0B[4]=pk(B1.x,B1.x); d0B[5]=pk(B1.y,B1.y); d0B[6]=pk(B1.z,B1.z); d0B[7]=pk(B1.w,B1.w);
    d0B[8]=pk(B2.x,B2.x); d0B[9]=pk(B2.y,B2.y); d0B[10]=pk(B2.z,B2.z); d0B[11]=pk(B2.w,B2.w);

    // identities (scalar) + dup buffers
    float id1A[12], id1B[12], id2A[12], id2B[12], id3A[10], id3B[10];
    float id4A[10], id4B[10], id5A[8],  id5B[8],  id6A[8],  id6B[8];
    u64 d1A[12], d1B[12], d2A[12], d2B[12], d3A[10], d3B[10];
    u64 d4A[10], d4B[10], d5A[8],  d5B[8],  d6A[8],  d6B[8];
    u64 d7A[6],  d7B[6],  d8A[8],  d8B[8],  d9A[8],  d9B[8];
    u64 dAA[10], dAB[10], dBA[10], dBB[10], dCA[12], dCB[12], dDA[12], dDB[12];
    float lgA[2], lgB[2];

    layerFP<12,12,true ,false,true ,true >(ws+  0, bs+ 0, d0A,d0B, d1A,d1B, nullptr,nullptr, id1A,id1B); // fc1
    layerFP<12,11,true ,false,true ,true >(ws+ 36, bs+ 6, d1A,d1B, d2A,d2B, nullptr,nullptr, id2A,id2B); // fc2
    layerFP<11,10,true ,false,true ,true >(ws+ 72, bs+12, d2A,d2B, d3A,d3B, nullptr,nullptr, id3A,id3B); // fc3
    layerFP<10, 9,true ,false,true ,true >(ws+102, bs+17, d3A,d3B, d4A,d4B, nullptr,nullptr, id4A,id4B); // fc4
    layerFP< 9, 8,true ,false,true ,true >(ws+127, bs+22, d4A,d4B, d5A,d5B, nullptr,nullptr, id5A,id5B); // fc5
    layerFP< 8, 7,true ,false,true ,true >(ws+147, bs+26, d5A,d5B, d6A,d6B, nullptr,nullptr, id6A,id6B); // fc6
    layerFP< 7, 6,true ,false,false,true >(ws+163, bs+30, d6A,d6B, d7A,d7B, nullptr,nullptr, nullptr,nullptr); // fc7
    layerFP< 6, 7,true ,true ,false,true >(ws+175, bs+33, d7A,d7B, d8A,d8B, id6A,id6B, nullptr,nullptr); // fc8
    layerFP< 7, 8,true ,true ,false,true >(ws+187, bs+37, d8A,d8B, d9A,d9B, id5A,id5B, nullptr,nullptr); // fc9
    layerFP< 8, 9,true ,true ,false,true >(ws+203, bs+41, d9A,d9B, dAA,dAB, id4A,id4B, nullptr,nullptr); // fc10
    layerFP< 9,10,true ,true ,false,true >(ws+223, bs+46, dAA,dAB, dBA,dBB, id3A,id3B, nullptr,nullptr); // fc11
    layerFP<10,11,true ,true ,false,true >(ws+248, bs+51, dBA,dBB, dCA,dCB, id2A,id2B, nullptr,nullptr); // fc12
    layerFP<11,12,true ,true ,false,true >(ws+278, bs+57, dCA,dCB, dDA,dDB, id1A,id1B, nullptr,nullptr); // fc13
    layerFP<12, 2,false,false,true ,false>(ws+314, bs+63, dDA,dDB, nullptr,nullptr, nullptr,nullptr, lgA,lgB); // fc14

    // ---- softmax over the 2 classes, per row ----
    float2 outA, outB;
    {
        float m = fmaxf(lgA[0], lgA[1]);
        float e0 = __expf(lgA[0] - m), e1 = __expf(lgA[1] - m);
        float inv = __fdividef(1.f, e0 + e1);
        outA = make_float2(e0 * inv, e1 * inv);
    }
    {
        float m = fmaxf(lgB[0], lgB[1]);
        float e0 = __expf(lgB[0] - m), e1 = __expf(lgB[1] - m);
        float inv = __fdividef(1.f, e0 + e1);
        outB = make_float2(e0 * inv, e1 * inv);
    }

    float2* o = (float2*)p.out;
    o[r0] = outA;
    o[r1] = outB;
}

extern "C" void kernel_launch(void* const* d_in, const int* in_sizes, int n_in,
                              void* d_out, int out_size)
{
    (void)n_in; (void)out_size;
    Params p;
    p.x = (const float*)d_in[0];
#pragma unroll
    for (int i = 0; i < NL; ++i) {
        p.w[i] = (const float*)d_in[1 + 2 * i];
        p.b[i] = (const float*)d_in[2 + 2 * i];
    }
    p.out = (float*)d_out;
    p.n = in_sizes[0] / 12;

    const int pairs = (p.n + 1) / 2;
    const int blocks = (pairs + 127) / 128;
    csnet14_kernel<<<blocks, 128>>>(p);
}